// round 3
// baseline (speedup 1.0000x reference)
#include <cuda_runtime.h>
#include <cuda_bf16.h>
#include <math.h>

// Problem constants
#define Bb   64
#define Nn   512
#define Cc   768
#define Hh   12
#define HD   64
#define BH   (Bb*Hh)          // 768
#define Mrows (Bb*Nn)         // 32768

// Scratch (allocation-free rule: __device__ globals)
__device__ float gQ[BH * Nn * HD];
__device__ float gK[BH * Nn * HD];
__device__ float gV[BH * Nn * HD];
__device__ float gAO[Mrows * Cc];

// ---------------------------------------------------------------------------
// SGEMM-NT: Y[m,j] = sum_k A[m,k]*B[j,k]   (A row-major MxK, B row-major NxK)
// BM=BN=128, BK=8, 256 threads, 8x8 per thread.
// Software-pipelined: next k-tile's LDG issued before current FMA block, so
// global-load latency is hidden under the 512-FMA compute phase instead of
// being exposed between the two barriers.
// MODE 0: out[m*N + j] = acc + bias[j]
// MODE 1: scatter into gQ/gK/gV per qkv column mapping
// ---------------------------------------------------------------------------
template<int MODE>
__global__ void __launch_bounds__(256) gemm_nt(
    const float* __restrict__ A, const float* __restrict__ B,
    const float* __restrict__ bias, float* __restrict__ out,
    int M, int N, int K)
{
    __shared__ float As[8][128];
    __shared__ float Bs[8][128];

    const int t  = threadIdx.x;
    const int bx = blockIdx.x;        // N tile
    const int by = blockIdx.y;        // M tile
    const int arow = t >> 1;          // 0..127
    const int ac4  = (t & 1) << 2;    // 0 or 4
    const int tx = t & 15;
    const int ty = t >> 4;

    const float* Aptr = A + (size_t)(by * 128 + arow) * K + ac4;
    const float* Bptr = B + (size_t)(bx * 128 + arow) * K + ac4;

    float acc[8][8];
    #pragma unroll
    for (int i = 0; i < 8; i++)
        #pragma unroll
        for (int j = 0; j < 8; j++) acc[i][j] = 0.0f;

    // prologue: first tile's loads
    float4 av = *(const float4*)(Aptr);
    float4 bv = *(const float4*)(Bptr);

    for (int k0 = 0; k0 < K; k0 += 8) {
        __syncthreads();
        As[ac4+0][arow] = av.x; As[ac4+1][arow] = av.y;
        As[ac4+2][arow] = av.z; As[ac4+3][arow] = av.w;
        Bs[ac4+0][arow] = bv.x; Bs[ac4+1][arow] = bv.y;
        Bs[ac4+2][arow] = bv.z; Bs[ac4+3][arow] = bv.w;
        __syncthreads();
        // prefetch next tile (landing hidden under the FMA block below)
        if (k0 + 8 < K) {
            av = *(const float4*)(Aptr + k0 + 8);
            bv = *(const float4*)(Bptr + k0 + 8);
        }
        #pragma unroll
        for (int k = 0; k < 8; k++) {
            float4 a0 = *(const float4*)&As[k][ty*8];
            float4 a1 = *(const float4*)&As[k][ty*8+4];
            float4 b0 = *(const float4*)&Bs[k][tx*8];
            float4 b1 = *(const float4*)&Bs[k][tx*8+4];
            float ar[8] = {a0.x,a0.y,a0.z,a0.w,a1.x,a1.y,a1.z,a1.w};
            float br[8] = {b0.x,b0.y,b0.z,b0.w,b1.x,b1.y,b1.z,b1.w};
            #pragma unroll
            for (int i = 0; i < 8; i++)
                #pragma unroll
                for (int j = 0; j < 8; j++)
                    acc[i][j] = fmaf(ar[i], br[j], acc[i][j]);
        }
    }

    if (MODE == 0) {
        const int m0 = by * 128 + ty * 8;
        const int j0 = bx * 128 + tx * 8;
        float bb[8];
        #pragma unroll
        for (int c = 0; c < 8; c++) bb[c] = bias[j0 + c];
        #pragma unroll
        for (int r = 0; r < 8; r++) {
            float4 v0 = make_float4(acc[r][0]+bb[0], acc[r][1]+bb[1],
                                    acc[r][2]+bb[2], acc[r][3]+bb[3]);
            float4 v1 = make_float4(acc[r][4]+bb[4], acc[r][5]+bb[5],
                                    acc[r][6]+bb[6], acc[r][7]+bb[7]);
            *(float4*)(out + (size_t)(m0 + r) * N + j0)     = v0;
            *(float4*)(out + (size_t)(m0 + r) * N + j0 + 4) = v1;
        }
    } else {
        // qkv scatter: column j -> (three=j/768, h=(j%768)/64, d=j%64)
        const int j0    = bx * 128 + tx * 8;
        const int three = (bx * 128) / Cc;            // uniform per block
        const int h     = (j0 % Cc) / HD;             // uniform per thread
        const int d0    = j0 % HD;                    // 8-aligned
        const int b     = (by * 128) / Nn;            // uniform per block
        const int nbase = (by * 128) % Nn + ty * 8;
        float* basep = (three == 0) ? gQ : (three == 1) ? gK : gV;
        float* dst = basep + ((size_t)(b * Hh + h) * Nn) * HD + d0;
        #pragma unroll
        for (int r = 0; r < 8; r++) {
            const size_t off = (size_t)(nbase + r) * HD;
            *(float4*)(dst + off)     = make_float4(acc[r][0], acc[r][1], acc[r][2], acc[r][3]);
            *(float4*)(dst + off + 4) = make_float4(acc[r][4], acc[r][5], acc[r][6], acc[r][7]);
        }
    }
}

// ---------------------------------------------------------------------------
// Fast exp for x <= 0 (post max-subtraction): pure-FFMA 2^f, avoids MUFU wall
// ---------------------------------------------------------------------------
__device__ __forceinline__ float exp_nm(float x) {
    x = fmaxf(x, -80.0f);
    const float L2E = 1.4426950408889634f;
    float y = x * L2E;
    float r = rintf(y);
    float f = fmaf(x, L2E, -r);
    // 2^f, |f| <= 0.5, Taylor deg 6 (rel err ~3e-8)
    float p = 1.5403530e-4f;
    p = fmaf(p, f, 1.3333558e-3f);
    p = fmaf(p, f, 9.6181291e-3f);
    p = fmaf(p, f, 5.5504109e-2f);
    p = fmaf(p, f, 2.4022650e-1f);
    p = fmaf(p, f, 6.9314718e-1f);
    p = fmaf(p, f, 1.0f);
    int e = (int)r;
    float sc = __int_as_float((e + 127) << 23);
    return p * sc;
}

// ---------------------------------------------------------------------------
// Fused attention: one block = (b,h, 64-row slab). Full 64x512 score tile in
// SMEM, rel-pos bias via 575-entry SMEM LUT, register softmax, streamed P@V.
// ---------------------------------------------------------------------------
#define SQ_F  (64*64)      // 4096   sQ transposed [k][row]
#define SKV_F (128*64)     // 8192   K tile transposed [k][j] / V tile [j][d]
#define SS_F  (64*512)     // 32768  scores
#define SB_F  576          // bias LUT
#define ATTN_SMEM_BYTES ((SQ_F + SKV_F + SS_F + SB_F) * 4)

__global__ void __launch_bounds__(256) attn_kernel(const float* __restrict__ bias_table)
{
    const int rb = blockIdx.x;       // 0..7 row slab
    const int bh = blockIdx.y;       // 0..767
    const int h  = bh % Hh;
    const int b  = bh / Hh;

    extern __shared__ float sm[];
    float* sQ  = sm;
    float* sKV = sm + SQ_F;
    float* sS  = sKV + SKV_F;
    float* sB  = sS + SS_F;

    const int tid = threadIdx.x;
    const int tx = tid & 15, ty = tid >> 4;

    const float* Qg = gQ + ((size_t)bh * Nn + rb * 64) * HD;
    const float* Kg = gK + (size_t)bh * Nn * HD;
    const float* Vg = gV + (size_t)bh * Nn * HD;

    // load Q slab transposed: sQ[k*64 + row]
    #pragma unroll
    for (int u = 0; u < 4; u++) {
        int idx = tid + 256 * u;           // 0..1023
        int row = idx >> 4;
        int d0  = (idx & 15) << 2;
        float4 v = *(const float4*)(Qg + row * HD + d0);
        sQ[(d0+0)*64 + row] = v.x;
        sQ[(d0+1)*64 + row] = v.y;
        sQ[(d0+2)*64 + row] = v.z;
        sQ[(d0+3)*64 + row] = v.w;
    }
    // bias LUT: index o = i - j + 511 (i local row, j global col), o in [0,574]
    for (int o = tid; o < 575; o += 256)
        sB[o] = bias_table[(o + rb * 64) * Hh + h];

    // ---- scores: S = 0.125 * Q K^T + bias ----
    for (int kt = 0; kt < 4; kt++) {
        __syncthreads();
        #pragma unroll
        for (int u = 0; u < 8; u++) {
            int idx = tid + 256 * u;       // 0..2047
            int j  = idx >> 4;
            int k0 = (idx & 15) << 2;
            float4 v = *(const float4*)(Kg + (kt*128 + j) * HD + k0);
            sKV[(k0+0)*128 + j] = v.x;
            sKV[(k0+1)*128 + j] = v.y;
            sKV[(k0+2)*128 + j] = v.z;
            sKV[(k0+3)*128 + j] = v.w;
        }
        __syncthreads();

        float acc[4][8];
        #pragma unroll
        for (int r = 0; r < 4; r++)
            #pragma unroll
            for (int c = 0; c < 8; c++) acc[r][c] = 0.0f;

        #pragma unroll 4
        for (int k = 0; k < 64; k++) {
            float4 b0 = *(const float4*)&sKV[k*128 + tx*8];
            float4 b1 = *(const float4*)&sKV[k*128 + tx*8 + 4];
            float bc[8] = {b0.x,b0.y,b0.z,b0.w,b1.x,b1.y,b1.z,b1.w};
            float a0 = sQ[k*64 + ty*4 + 0];
            float a1 = sQ[k*64 + ty*4 + 1];
            float a2 = sQ[k*64 + ty*4 + 2];
            float a3 = sQ[k*64 + ty*4 + 3];
            #pragma unroll
            for (int c = 0; c < 8; c++) {
                acc[0][c] = fmaf(a0, bc[c], acc[0][c]);
                acc[1][c] = fmaf(a1, bc[c], acc[1][c]);
                acc[2][c] = fmaf(a2, bc[c], acc[2][c]);
                acc[3][c] = fmaf(a3, bc[c], acc[3][c]);
            }
        }
        #pragma unroll
        for (int r = 0; r < 4; r++) {
            const int i = ty*4 + r;
            #pragma unroll
            for (int c = 0; c < 8; c++) {
                const int j = kt*128 + tx*8 + c;
                sS[i*512 + j] = fmaf(acc[r][c], 0.125f, sB[i - j + 511]);
            }
        }
    }
    __syncthreads();

    // ---- softmax (each warp owns 8 rows) ----
    {
        const int warp = tid >> 5, lane = tid & 31;
        for (int rr = 0; rr < 8; rr++) {
            const int row = warp * 8 + rr;
            float v[16];
            float mx = -1e30f;
            #pragma unroll
            for (int u = 0; u < 16; u++) {
                v[u] = sS[row*512 + lane + 32*u];
                mx = fmaxf(mx, v[u]);
            }
            #pragma unroll
            for (int o = 16; o >= 1; o >>= 1)
                mx = fmaxf(mx, __shfl_xor_sync(0xffffffffu, mx, o));
            float s = 0.0f;
            #pragma unroll
            for (int u = 0; u < 16; u++) { v[u] = exp_nm(v[u] - mx); s += v[u]; }
            #pragma unroll
            for (int o = 16; o >= 1; o >>= 1)
                s += __shfl_xor_sync(0xffffffffu, s, o);
            float inv = 1.0f / s;
            #pragma unroll
            for (int u = 0; u < 16; u++)
                sS[row*512 + lane + 32*u] = v[u] * inv;
        }
    }

    // ---- O = P @ V ----
    float oacc[4][4];
    #pragma unroll
    for (int r = 0; r < 4; r++)
        #pragma unroll
        for (int c = 0; c < 4; c++) oacc[r][c] = 0.0f;

    for (int vt = 0; vt < 4; vt++) {
        __syncthreads();
        #pragma unroll
        for (int u = 0; u < 8; u++) {
            int idx = tid + 256 * u;       // 0..2047 float4s
            float4 v = *(const float4*)(Vg + (size_t)vt*128*HD + idx*4);
            *(float4*)&sKV[idx*4] = v;     // natural [j][d] layout
        }
        __syncthreads();
        #pragma unroll 4
        for (int j = 0; j < 128; j++) {
            float4 bv = *(const float4*)&sKV[j*64 + tx*4];
            float a0 = sS[(ty*4+0)*512 + vt*128 + j];
            float a1 = sS[(ty*4+1)*512 + vt*128 + j];
            float a2 = sS[(ty*4+2)*512 + vt*128 + j];
            float a3 = sS[(ty*4+3)*512 + vt*128 + j];
            oacc[0][0]=fmaf(a0,bv.x,oacc[0][0]); oacc[0][1]=fmaf(a0,bv.y,oacc[0][1]);
            oacc[0][2]=fmaf(a0,bv.z,oacc[0][2]); oacc[0][3]=fmaf(a0,bv.w,oacc[0][3]);
            oacc[1][0]=fmaf(a1,bv.x,oacc[1][0]); oacc[1][1]=fmaf(a1,bv.y,oacc[1][1]);
            oacc[1][2]=fmaf(a1,bv.z,oacc[1][2]); oacc[1][3]=fmaf(a1,bv.w,oacc[1][3]);
            oacc[2][0]=fmaf(a2,bv.x,oacc[2][0]); oacc[2][1]=fmaf(a2,bv.y,oacc[2][1]);
            oacc[2][2]=fmaf(a2,bv.z,oacc[2][2]); oacc[2][3]=fmaf(a2,bv.w,oacc[2][3]);
            oacc[3][0]=fmaf(a3,bv.x,oacc[3][0]); oacc[3][1]=fmaf(a3,bv.y,oacc[3][1]);
            oacc[3][2]=fmaf(a3,bv.z,oacc[3][2]); oacc[3][3]=fmaf(a3,bv.w,oacc[3][3]);
        }
    }

    // write [B, N, H*hd]
    float* Og = gAO + ((size_t)(b * Nn + rb * 64)) * Cc + h * HD;
    #pragma unroll
    for (int r = 0; r < 4; r++) {
        const int i = ty*4 + r;
        *(float4*)(Og + (size_t)i * Cc + tx*4) =
            make_float4(oacc[r][0], oacc[r][1], oacc[r][2], oacc[r][3]);
    }
}

// Proj GEMM reads gAO directly (avoids symbol-address plumbing)
__global__ void __launch_bounds__(256) gemm_proj(
    const float* __restrict__ W, const float* __restrict__ bias,
    float* __restrict__ out)
{
    __shared__ float As[8][128];
    __shared__ float Bs[8][128];
    const int t  = threadIdx.x;
    const int bx = blockIdx.x;
    const int by = blockIdx.y;
    const int arow = t >> 1;
    const int ac4  = (t & 1) << 2;
    const int tx = t & 15, ty = t >> 4;
    const int K = Cc, N = Cc;

    const float* Aptr = gAO + (size_t)(by * 128 + arow) * K + ac4;
    const float* Bptr = W   + (size_t)(bx * 128 + arow) * K + ac4;

    float acc[8][8];
    #pragma unroll
    for (int i = 0; i < 8; i++)
        #pragma unroll
        for (int j = 0; j < 8; j++) acc[i][j] = 0.0f;

    float4 av = *(const float4*)(Aptr);
    float4 bv = *(const float4*)(Bptr);

    for (int k0 = 0; k0 < K; k0 += 8) {
        __syncthreads();
        As[ac4+0][arow] = av.x; As[ac4+1][arow] = av.y;
        As[ac4+2][arow] = av.z; As[ac4+3][arow] = av.w;
        Bs[ac4+0][arow] = bv.x; Bs[ac4+1][arow] = bv.y;
        Bs[ac4+2][arow] = bv.z; Bs[ac4+3][arow] = bv.w;
        __syncthreads();
        if (k0 + 8 < K) {
            av = *(const float4*)(Aptr + k0 + 8);
            bv = *(const float4*)(Bptr + k0 + 8);
        }
        #pragma unroll
        for (int k = 0; k < 8; k++) {
            float4 a0 = *(const float4*)&As[k][ty*8];
            float4 a1 = *(const float4*)&As[k][ty*8+4];
            float4 b0 = *(const float4*)&Bs[k][tx*8];
            float4 b1 = *(const float4*)&Bs[k][tx*8+4];
            float ar[8] = {a0.x,a0.y,a0.z,a0.w,a1.x,a1.y,a1.z,a1.w};
            float br[8] = {b0.x,b0.y,b0.z,b0.w,b1.x,b1.y,b1.z,b1.w};
            #pragma unroll
            for (int i = 0; i < 8; i++)
                #pragma unroll
                for (int j = 0; j < 8; j++)
                    acc[i][j] = fmaf(ar[i], br[j], acc[i][j]);
        }
    }
    const int m0 = by * 128 + ty * 8;
    const int j0 = bx * 128 + tx * 8;
    float bb[8];
    #pragma unroll
    for (int c = 0; c < 8; c++) bb[c] = bias[j0 + c];
    #pragma unroll
    for (int r = 0; r < 8; r++) {
        float4 v0 = make_float4(acc[r][0]+bb[0], acc[r][1]+bb[1],
                                acc[r][2]+bb[2], acc[r][3]+bb[3]);
        float4 v1 = make_float4(acc[r][4]+bb[4], acc[r][5]+bb[5],
                                acc[r][6]+bb[6], acc[r][7]+bb[7]);
        *(float4*)(out + (size_t)(m0 + r) * N + j0)     = v0;
        *(float4*)(out + (size_t)(m0 + r) * N + j0 + 4) = v1;
    }
}

extern "C" void kernel_launch(void* const* d_in, const int* in_sizes, int n_in,
                              void* d_out, int out_size)
{
    (void)in_sizes; (void)n_in; (void)out_size;
    const float* x          = (const float*)d_in[0];
    const float* qkv_w      = (const float*)d_in[1];
    const float* proj_w     = (const float*)d_in[2];
    const float* proj_b     = (const float*)d_in[3];
    const float* bias_table = (const float*)d_in[4];
    float* out = (float*)d_out;

    cudaFuncSetAttribute(attn_kernel,
        cudaFuncAttributeMaxDynamicSharedMemorySize, ATTN_SMEM_BYTES);

    // 1) QKV projection with scatter into gQ/gK/gV
    gemm_nt<1><<<dim3(3*Cc/128, Mrows/128), 256>>>(
        x, qkv_w, nullptr, nullptr, Mrows, 3*Cc, Cc);

    // 2) Fused attention
    attn_kernel<<<dim3(Nn/64, BH), 256, ATTN_SMEM_BYTES>>>(bias_table);

    // 3) Output projection
    gemm_proj<<<dim3(Cc/128, Mrows/128), 256>>>(proj_w, proj_b, out);
}

// round 4
// speedup vs baseline: 1.5555x; 1.5555x over previous
#include <cuda_runtime.h>
#include <cuda_bf16.h>
#include <math.h>
#include <stdint.h>

// Problem constants
#define Bb   64
#define Nn   512
#define Cc   768
#define Hh   12
#define HD   64
#define BH   (Bb*Hh)          // 768
#define Mrows (Bb*Nn)         // 32768

// Scratch (allocation-free rule: __device__ globals)
__device__ float gQ[BH * Nn * HD];
__device__ float gK[BH * Nn * HD];
__device__ float gV[BH * Nn * HD];
__device__ float gAO[Mrows * Cc];

// ---------------------------------------------------------------------------
// tf32 helpers
// ---------------------------------------------------------------------------
__device__ __forceinline__ uint32_t f2tf32(float f) {
    uint32_t u;
    asm("cvt.rna.tf32.f32 %0, %1;" : "=r"(u) : "f"(f));
    return u;
}

__device__ __forceinline__ void mma_tf32(float c[4], const uint32_t a[4],
                                         const uint32_t b[2]) {
    asm volatile(
        "mma.sync.aligned.m16n8k8.row.col.f32.tf32.tf32.f32 "
        "{%0,%1,%2,%3}, {%4,%5,%6,%7}, {%8,%9}, {%0,%1,%2,%3};"
        : "+f"(c[0]), "+f"(c[1]), "+f"(c[2]), "+f"(c[3])
        : "r"(a[0]), "r"(a[1]), "r"(a[2]), "r"(a[3]),
          "r"(b[0]), "r"(b[1]));
}

// ---------------------------------------------------------------------------
// tf32 tensor-core GEMM-NT: Y[m,j] = sum_k A[m,k]*B[j,k]
// Block tile 128x128, k-stage 32, 8 warps (2m x 4n), warp tile 64x32.
// SMEM is fragment-major so reads are LDS.128/LDS.64 straight into mma frags:
//   Asf[k8][m16][lane][reg4]  (k8 stride padded +4 words)
//   Bsf[k8][n8 ][lane][reg2]
// Fragment ownership (m16n8k8 tf32):
//   A elem (r,kk): lane=4*(r&7)+(kk&3), reg=(r>>3)+2*(kk>>2)
//   B elem (kk,n): lane=4*n+(kk&3),     reg=kk>>2
//   C regs: c0=(g,2t) c1=(g,2t+1) c2=(g+8,2t) c3=(g+8,2t+1), g=lane>>2,t=lane&3
// MODE 0: out[m*N+j] = acc + bias[j]
// MODE 1: scatter into gQ/gK/gV per qkv column mapping
// ---------------------------------------------------------------------------
#define K8STRIDE 1028          // 8*32*4 (= 16*32*2) + 4 pad words

template<int MODE>
__global__ void __launch_bounds__(256) gemm_tf32(
    const float* __restrict__ A, const float* __restrict__ B,
    const float* __restrict__ bias, float* __restrict__ out,
    int M, int N, int K)
{
    __shared__ uint32_t Asf[4 * K8STRIDE];
    __shared__ uint32_t Bsf[4 * K8STRIDE];

    const int t    = threadIdx.x;
    const int lane = t & 31;
    const int w    = t >> 5;
    const int wm   = w & 1;          // 0..1 -> m offset 0/64
    const int wn   = w >> 1;         // 0..3 -> n offset 0/32/64/96
    const int bx   = blockIdx.x;
    const int by   = blockIdx.y;

    const float* Ag = A + (size_t)(by * 128) * K;
    const float* Bg = B + (size_t)(bx * 128) * K;

    float c[4][4][4];
    #pragma unroll
    for (int i = 0; i < 4; i++)
        #pragma unroll
        for (int j = 0; j < 4; j++)
            #pragma unroll
            for (int r = 0; r < 4; r++) c[i][j][r] = 0.0f;

    // GMEM staging: 1024 float4 per stage per matrix; 4 per thread.
    // flat = t + 256*u : row = flat>>3 (8 float4 per 32-float row), kc=(flat&7)*4
    float4 av[4], bv[4];
    #pragma unroll
    for (int u = 0; u < 4; u++) {
        const int flat = t + 256 * u;
        const int row = flat >> 3, kc = (flat & 7) << 2;
        av[u] = *(const float4*)(Ag + (size_t)row * K + kc);
        bv[u] = *(const float4*)(Bg + (size_t)row * K + kc);
    }

    for (int ks = 0; ks < K; ks += 32) {
        __syncthreads();
        // scatter-store fragments (with tf32 rounding)
        #pragma unroll
        for (int u = 0; u < 4; u++) {
            const int flat = t + 256 * u;
            const int row  = flat >> 3;
            const int kc   = (flat & 7) << 2;
            const int k8   = kc >> 3;
            const int half = (kc >> 2) & 1;
            const float va[4] = {av[u].x, av[u].y, av[u].z, av[u].w};
            const float vb[4] = {bv[u].x, bv[u].y, bv[u].z, bv[u].w};
            // A: element (r, kk) of m16-subtile
            {
                const int m16 = row >> 4, r = row & 15;
                const int reg = (r >> 3) + 2 * half;
                const int base = k8 * K8STRIDE + (m16 * 32 + 4 * (r & 7)) * 4 + reg;
                #pragma unroll
                for (int e = 0; e < 4; e++)
                    Asf[base + e * 4] = f2tf32(va[e]);
            }
            // B: element (kk, n) of n8-subtile (B row index is n)
            {
                const int n8 = row >> 3, nn = row & 7;
                const int base = k8 * K8STRIDE + (n8 * 32 + 4 * nn) * 2 + half;
                #pragma unroll
                for (int e = 0; e < 4; e++)
                    Bsf[base + e * 2] = f2tf32(vb[e]);
            }
        }
        __syncthreads();

        // prefetch next stage (lands under the MMA block)
        if (ks + 32 < K) {
            #pragma unroll
            for (int u = 0; u < 4; u++) {
                const int flat = t + 256 * u;
                const int row = flat >> 3, kc = (flat & 7) << 2;
                av[u] = *(const float4*)(Ag + (size_t)row * K + ks + 32 + kc);
                bv[u] = *(const float4*)(Bg + (size_t)row * K + ks + 32 + kc);
            }
        }

        // compute: 4 k8-steps x 16 mma
        #pragma unroll
        for (int k8 = 0; k8 < 4; k8++) {
            uint32_t a[4][4];
            uint32_t b[4][2];
            #pragma unroll
            for (int i = 0; i < 4; i++) {
                const uint4 v = *(const uint4*)
                    &Asf[k8 * K8STRIDE + ((wm * 4 + i) * 32 + lane) * 4];
                a[i][0] = v.x; a[i][1] = v.y; a[i][2] = v.z; a[i][3] = v.w;
            }
            #pragma unroll
            for (int j = 0; j < 4; j++) {
                const uint2 v = *(const uint2*)
                    &Bsf[k8 * K8STRIDE + ((wn * 4 + j) * 32 + lane) * 2];
                b[j][0] = v.x; b[j][1] = v.y;
            }
            #pragma unroll
            for (int i = 0; i < 4; i++)
                #pragma unroll
                for (int j = 0; j < 4; j++)
                    mma_tf32(c[i][j], a[i], b[j]);
        }
    }

    const int g  = lane >> 2;
    const int tq = lane & 3;

    if (MODE == 0) {
        const int m_base = by * 128 + wm * 64;
        const int n_base = bx * 128 + wn * 32;
        #pragma unroll
        for (int j = 0; j < 4; j++) {
            const int n = n_base + j * 8 + 2 * tq;
            const float b0v = bias[n], b1v = bias[n + 1];
            #pragma unroll
            for (int i = 0; i < 4; i++) {
                const int m0r = m_base + i * 16 + g;
                *(float2*)(out + (size_t)m0r * N + n) =
                    make_float2(c[i][j][0] + b0v, c[i][j][1] + b1v);
                *(float2*)(out + (size_t)(m0r + 8) * N + n) =
                    make_float2(c[i][j][2] + b0v, c[i][j][3] + b1v);
            }
        }
    } else {
        // qkv scatter: column jg -> (three=jg/768, h=(jg%768)/64, d=jg%64)
        const int n_base = bx * 128 + wn * 32;
        const int bb   = (by * 128) / Nn;           // uniform per block
        const int m_in = (by * 128) % Nn + wm * 64; // row within sequence
        #pragma unroll
        for (int j = 0; j < 4; j++) {
            const int jg    = n_base + j * 8 + 2 * tq;
            const int three = jg / Cc;
            const int h     = (jg % Cc) / HD;
            const int d     = jg % HD;               // even -> float2 safe
            float* basep = (three == 0) ? gQ : (three == 1) ? gK : gV;
            float* dst = basep + ((size_t)(bb * Hh + h) * Nn) * HD + d;
            #pragma unroll
            for (int i = 0; i < 4; i++) {
                const int nr = m_in + i * 16 + g;
                *(float2*)(dst + (size_t)nr * HD) =
                    make_float2(c[i][j][0], c[i][j][1]);
                *(float2*)(dst + (size_t)(nr + 8) * HD) =
                    make_float2(c[i][j][2], c[i][j][3]);
            }
        }
    }
}

// ---------------------------------------------------------------------------
// Fast exp for x <= 0 (post max-subtraction): pure-FFMA 2^f, avoids MUFU wall
// ---------------------------------------------------------------------------
__device__ __forceinline__ float exp_nm(float x) {
    x = fmaxf(x, -80.0f);
    const float L2E = 1.4426950408889634f;
    float y = x * L2E;
    float r = rintf(y);
    float f = fmaf(x, L2E, -r);
    float p = 1.5403530e-4f;
    p = fmaf(p, f, 1.3333558e-3f);
    p = fmaf(p, f, 9.6181291e-3f);
    p = fmaf(p, f, 5.5504109e-2f);
    p = fmaf(p, f, 2.4022650e-1f);
    p = fmaf(p, f, 6.9314718e-1f);
    p = fmaf(p, f, 1.0f);
    int e = (int)r;
    float sc = __int_as_float((e + 127) << 23);
    return p * sc;
}

// ---------------------------------------------------------------------------
// Fused attention: one block = (b,h, 64-row slab). Full 64x512 score tile in
// SMEM, rel-pos bias via 575-entry SMEM LUT, register softmax, streamed P@V.
// ---------------------------------------------------------------------------
#define SQ_F  (64*64)      // 4096   sQ transposed [k][row]
#define SKV_F (128*64)     // 8192   K tile transposed [k][j] / V tile [j][d]
#define SS_F  (64*512)     // 32768  scores
#define SB_F  576          // bias LUT
#define ATTN_SMEM_BYTES ((SQ_F + SKV_F + SS_F + SB_F) * 4)

__global__ void __launch_bounds__(256) attn_kernel(const float* __restrict__ bias_table)
{
    const int rb = blockIdx.x;       // 0..7 row slab
    const int bh = blockIdx.y;       // 0..767
    const int h  = bh % Hh;
    const int b  = bh / Hh;

    extern __shared__ float sm[];
    float* sQ  = sm;
    float* sKV = sm + SQ_F;
    float* sS  = sKV + SKV_F;
    float* sB  = sS + SS_F;

    const int tid = threadIdx.x;
    const int tx = tid & 15, ty = tid >> 4;

    const float* Qg = gQ + ((size_t)bh * Nn + rb * 64) * HD;
    const float* Kg = gK + (size_t)bh * Nn * HD;
    const float* Vg = gV + (size_t)bh * Nn * HD;

    // load Q slab transposed: sQ[k*64 + row]
    #pragma unroll
    for (int u = 0; u < 4; u++) {
        int idx = tid + 256 * u;           // 0..1023
        int row = idx >> 4;
        int d0  = (idx & 15) << 2;
        float4 v = *(const float4*)(Qg + row * HD + d0);
        sQ[(d0+0)*64 + row] = v.x;
        sQ[(d0+1)*64 + row] = v.y;
        sQ[(d0+2)*64 + row] = v.z;
        sQ[(d0+3)*64 + row] = v.w;
    }
    // bias LUT: index o = i - j + 511 (i local row, j global col), o in [0,574]
    for (int o = tid; o < 575; o += 256)
        sB[o] = bias_table[(o + rb * 64) * Hh + h];

    // ---- scores: S = 0.125 * Q K^T + bias ----
    for (int kt = 0; kt < 4; kt++) {
        __syncthreads();
        #pragma unroll
        for (int u = 0; u < 8; u++) {
            int idx = tid + 256 * u;       // 0..2047
            int j  = idx >> 4;
            int k0 = (idx & 15) << 2;
            float4 v = *(const float4*)(Kg + (kt*128 + j) * HD + k0);
            sKV[(k0+0)*128 + j] = v.x;
            sKV[(k0+1)*128 + j] = v.y;
            sKV[(k0+2)*128 + j] = v.z;
            sKV[(k0+3)*128 + j] = v.w;
        }
        __syncthreads();

        float acc[4][8];
        #pragma unroll
        for (int r = 0; r < 4; r++)
            #pragma unroll
            for (int c = 0; c < 8; c++) acc[r][c] = 0.0f;

        #pragma unroll 4
        for (int k = 0; k < 64; k++) {
            float4 b0 = *(const float4*)&sKV[k*128 + tx*8];
            float4 b1 = *(const float4*)&sKV[k*128 + tx*8 + 4];
            float bc[8] = {b0.x,b0.y,b0.z,b0.w,b1.x,b1.y,b1.z,b1.w};
            float a0 = sQ[k*64 + ty*4 + 0];
            float a1 = sQ[k*64 + ty*4 + 1];
            float a2 = sQ[k*64 + ty*4 + 2];
            float a3 = sQ[k*64 + ty*4 + 3];
            #pragma unroll
            for (int c = 0; c < 8; c++) {
                acc[0][c] = fmaf(a0, bc[c], acc[0][c]);
                acc[1][c] = fmaf(a1, bc[c], acc[1][c]);
                acc[2][c] = fmaf(a2, bc[c], acc[2][c]);
                acc[3][c] = fmaf(a3, bc[c], acc[3][c]);
            }
        }
        #pragma unroll
        for (int r = 0; r < 4; r++) {
            const int i = ty*4 + r;
            #pragma unroll
            for (int c = 0; c < 8; c++) {
                const int j = kt*128 + tx*8 + c;
                sS[i*512 + j] = fmaf(acc[r][c], 0.125f, sB[i - j + 511]);
            }
        }
    }
    __syncthreads();

    // ---- softmax (each warp owns 8 rows) ----
    {
        const int warp = tid >> 5, lane = tid & 31;
        for (int rr = 0; rr < 8; rr++) {
            const int row = warp * 8 + rr;
            float v[16];
            float mx = -1e30f;
            #pragma unroll
            for (int u = 0; u < 16; u++) {
                v[u] = sS[row*512 + lane + 32*u];
                mx = fmaxf(mx, v[u]);
            }
            #pragma unroll
            for (int o = 16; o >= 1; o >>= 1)
                mx = fmaxf(mx, __shfl_xor_sync(0xffffffffu, mx, o));
            float s = 0.0f;
            #pragma unroll
            for (int u = 0; u < 16; u++) { v[u] = exp_nm(v[u] - mx); s += v[u]; }
            #pragma unroll
            for (int o = 16; o >= 1; o >>= 1)
                s += __shfl_xor_sync(0xffffffffu, s, o);
            float inv = 1.0f / s;
            #pragma unroll
            for (int u = 0; u < 16; u++)
                sS[row*512 + lane + 32*u] = v[u] * inv;
        }
    }

    // ---- O = P @ V ----
    float oacc[4][4];
    #pragma unroll
    for (int r = 0; r < 4; r++)
        #pragma unroll
        for (int c = 0; c < 4; c++) oacc[r][c] = 0.0f;

    for (int vt = 0; vt < 4; vt++) {
        __syncthreads();
        #pragma unroll
        for (int u = 0; u < 8; u++) {
            int idx = tid + 256 * u;       // 0..2047 float4s
            float4 v = *(const float4*)(Vg + (size_t)vt*128*HD + idx*4);
            *(float4*)&sKV[idx*4] = v;     // natural [j][d] layout
        }
        __syncthreads();
        #pragma unroll 4
        for (int j = 0; j < 128; j++) {
            float4 bv = *(const float4*)&sKV[j*64 + tx*4];
            float a0 = sS[(ty*4+0)*512 + vt*128 + j];
            float a1 = sS[(ty*4+1)*512 + vt*128 + j];
            float a2 = sS[(ty*4+2)*512 + vt*128 + j];
            float a3 = sS[(ty*4+3)*512 + vt*128 + j];
            oacc[0][0]=fmaf(a0,bv.x,oacc[0][0]); oacc[0][1]=fmaf(a0,bv.y,oacc[0][1]);
            oacc[0][2]=fmaf(a0,bv.z,oacc[0][2]); oacc[0][3]=fmaf(a0,bv.w,oacc[0][3]);
            oacc[1][0]=fmaf(a1,bv.x,oacc[1][0]); oacc[1][1]=fmaf(a1,bv.y,oacc[1][1]);
            oacc[1][2]=fmaf(a1,bv.z,oacc[1][2]); oacc[1][3]=fmaf(a1,bv.w,oacc[1][3]);
            oacc[2][0]=fmaf(a2,bv.x,oacc[2][0]); oacc[2][1]=fmaf(a2,bv.y,oacc[2][1]);
            oacc[2][2]=fmaf(a2,bv.z,oacc[2][2]); oacc[2][3]=fmaf(a2,bv.w,oacc[2][3]);
            oacc[3][0]=fmaf(a3,bv.x,oacc[3][0]); oacc[3][1]=fmaf(a3,bv.y,oacc[3][1]);
            oacc[3][2]=fmaf(a3,bv.z,oacc[3][2]); oacc[3][3]=fmaf(a3,bv.w,oacc[3][3]);
        }
    }

    // write [B, N, H*hd]
    float* Og = gAO + ((size_t)(b * Nn + rb * 64)) * Cc + h * HD;
    #pragma unroll
    for (int r = 0; r < 4; r++) {
        const int i = ty*4 + r;
        *(float4*)(Og + (size_t)i * Cc + tx*4) =
            make_float4(oacc[r][0], oacc[r][1], oacc[r][2], oacc[r][3]);
    }
}

extern "C" void kernel_launch(void* const* d_in, const int* in_sizes, int n_in,
                              void* d_out, int out_size)
{
    (void)in_sizes; (void)n_in; (void)out_size;
    const float* x          = (const float*)d_in[0];
    const float* qkv_w      = (const float*)d_in[1];
    const float* proj_w     = (const float*)d_in[2];
    const float* proj_b     = (const float*)d_in[3];
    const float* bias_table = (const float*)d_in[4];
    float* out = (float*)d_out;

    cudaFuncSetAttribute(attn_kernel,
        cudaFuncAttributeMaxDynamicSharedMemorySize, ATTN_SMEM_BYTES);

    void* gAO_ptr = nullptr;
    cudaGetSymbolAddress(&gAO_ptr, gAO);

    // 1) QKV projection (tf32 tensor cores) with scatter into gQ/gK/gV
    gemm_tf32<1><<<dim3(3*Cc/128, Mrows/128), 256>>>(
        x, qkv_w, nullptr, nullptr, Mrows, 3*Cc, Cc);

    // 2) Fused attention (fp32)
    attn_kernel<<<dim3(Nn/64, BH), 256, ATTN_SMEM_BYTES>>>(bias_table);

    // 3) Output projection (tf32 tensor cores)
    gemm_tf32<0><<<dim3(Cc/128, Mrows/128), 256>>>(
        (const float*)gAO_ptr, proj_w, proj_b, out, Mrows, Cc, Cc);
}

// round 13
// speedup vs baseline: 2.4000x; 1.5429x over previous
#include <cuda_runtime.h>
#include <cuda_bf16.h>
#include <math.h>
#include <stdint.h>

// Problem constants
#define Bb   64
#define Nn   512
#define Cc   768
#define Hh   12
#define HD   64
#define BH   (Bb*Hh)          // 768
#define Mrows (Bb*Nn)         // 32768

// Scratch (allocation-free rule: __device__ globals)
__device__ float gQ[BH * Nn * HD];
__device__ float gK[BH * Nn * HD];
__device__ float gV[BH * Nn * HD];
__device__ float gAO[Mrows * Cc];

// ---------------------------------------------------------------------------
// tf32 helpers
// ---------------------------------------------------------------------------
__device__ __forceinline__ uint32_t f2tf32(float f) {
    uint32_t u;
    asm("cvt.rna.tf32.f32 %0, %1;" : "=r"(u) : "f"(f));
    return u;
}

__device__ __forceinline__ void mma_tf32(float c[4], const uint32_t a[4],
                                         const uint32_t b[2]) {
    asm volatile(
        "mma.sync.aligned.m16n8k8.row.col.f32.tf32.tf32.f32 "
        "{%0,%1,%2,%3}, {%4,%5,%6,%7}, {%8,%9}, {%0,%1,%2,%3};"
        : "+f"(c[0]), "+f"(c[1]), "+f"(c[2]), "+f"(c[3])
        : "r"(a[0]), "r"(a[1]), "r"(a[2]), "r"(a[3]),
          "r"(b[0]), "r"(b[1]));
}

// ---------------------------------------------------------------------------
// tf32 tensor-core GEMM-NT: Y[m,j] = sum_k A[m,k]*B[j,k]
// Block tile 128x128, k-stage 32, 8 warps (2m x 4n), warp tile 64x32.
// Fragment-major SMEM staging. MODE 0: +bias -> out. MODE 1: qkv scatter.
// ---------------------------------------------------------------------------
#define K8STRIDE 1028          // 8*32*4 + 4 pad words

template<int MODE>
__global__ void __launch_bounds__(256) gemm_tf32(
    const float* __restrict__ A, const float* __restrict__ B,
    const float* __restrict__ bias, float* __restrict__ out,
    int M, int N, int K)
{
    __shared__ uint32_t Asf[4 * K8STRIDE];
    __shared__ uint32_t Bsf[4 * K8STRIDE];

    const int t    = threadIdx.x;
    const int lane = t & 31;
    const int w    = t >> 5;
    const int wm   = w & 1;
    const int wn   = w >> 1;
    const int bx   = blockIdx.x;
    const int by   = blockIdx.y;

    const float* Ag = A + (size_t)(by * 128) * K;
    const float* Bg = B + (size_t)(bx * 128) * K;

    float c[4][4][4];
    #pragma unroll
    for (int i = 0; i < 4; i++)
        #pragma unroll
        for (int j = 0; j < 4; j++)
            #pragma unroll
            for (int r = 0; r < 4; r++) c[i][j][r] = 0.0f;

    float4 av[4], bv[4];
    #pragma unroll
    for (int u = 0; u < 4; u++) {
        const int flat = t + 256 * u;
        const int row = flat >> 3, kc = (flat & 7) << 2;
        av[u] = *(const float4*)(Ag + (size_t)row * K + kc);
        bv[u] = *(const float4*)(Bg + (size_t)row * K + kc);
    }

    for (int ks = 0; ks < K; ks += 32) {
        __syncthreads();
        #pragma unroll
        for (int u = 0; u < 4; u++) {
            const int flat = t + 256 * u;
            const int row  = flat >> 3;
            const int kc   = (flat & 7) << 2;
            const int k8   = kc >> 3;
            const int half = (kc >> 2) & 1;
            const float va[4] = {av[u].x, av[u].y, av[u].z, av[u].w};
            const float vb[4] = {bv[u].x, bv[u].y, bv[u].z, bv[u].w};
            {
                const int m16 = row >> 4, r = row & 15;
                const int reg = (r >> 3) + 2 * half;
                const int base = k8 * K8STRIDE + (m16 * 32 + 4 * (r & 7)) * 4 + reg;
                #pragma unroll
                for (int e = 0; e < 4; e++)
                    Asf[base + e * 4] = f2tf32(va[e]);
            }
            {
                const int n8 = row >> 3, nn = row & 7;
                const int base = k8 * K8STRIDE + (n8 * 32 + 4 * nn) * 2 + half;
                #pragma unroll
                for (int e = 0; e < 4; e++)
                    Bsf[base + e * 2] = f2tf32(vb[e]);
            }
        }
        __syncthreads();

        if (ks + 32 < K) {
            #pragma unroll
            for (int u = 0; u < 4; u++) {
                const int flat = t + 256 * u;
                const int row = flat >> 3, kc = (flat & 7) << 2;
                av[u] = *(const float4*)(Ag + (size_t)row * K + ks + 32 + kc);
                bv[u] = *(const float4*)(Bg + (size_t)row * K + ks + 32 + kc);
            }
        }

        #pragma unroll
        for (int k8 = 0; k8 < 4; k8++) {
            uint32_t a[4][4];
            uint32_t b[4][2];
            #pragma unroll
            for (int i = 0; i < 4; i++) {
                const uint4 v = *(const uint4*)
                    &Asf[k8 * K8STRIDE + ((wm * 4 + i) * 32 + lane) * 4];
                a[i][0] = v.x; a[i][1] = v.y; a[i][2] = v.z; a[i][3] = v.w;
            }
            #pragma unroll
            for (int j = 0; j < 4; j++) {
                const uint2 v = *(const uint2*)
                    &Bsf[k8 * K8STRIDE + ((wn * 4 + j) * 32 + lane) * 2];
                b[j][0] = v.x; b[j][1] = v.y;
            }
            #pragma unroll
            for (int i = 0; i < 4; i++)
                #pragma unroll
                for (int j = 0; j < 4; j++)
                    mma_tf32(c[i][j], a[i], b[j]);
        }
    }

    const int g  = lane >> 2;
    const int tq = lane & 3;

    if (MODE == 0) {
        const int m_base = by * 128 + wm * 64;
        const int n_base = bx * 128 + wn * 32;
        #pragma unroll
        for (int j = 0; j < 4; j++) {
            const int n = n_base + j * 8 + 2 * tq;
            const float b0v = bias[n], b1v = bias[n + 1];
            #pragma unroll
            for (int i = 0; i < 4; i++) {
                const int m0r = m_base + i * 16 + g;
                *(float2*)(out + (size_t)m0r * N + n) =
                    make_float2(c[i][j][0] + b0v, c[i][j][1] + b1v);
                *(float2*)(out + (size_t)(m0r + 8) * N + n) =
                    make_float2(c[i][j][2] + b0v, c[i][j][3] + b1v);
            }
        }
    } else {
        const int n_base = bx * 128 + wn * 32;
        const int bb   = (by * 128) / Nn;
        const int m_in = (by * 128) % Nn + wm * 64;
        #pragma unroll
        for (int j = 0; j < 4; j++) {
            const int jg    = n_base + j * 8 + 2 * tq;
            const int three = jg / Cc;
            const int h     = (jg % Cc) / HD;
            const int d     = jg % HD;
            float* basep = (three == 0) ? gQ : (three == 1) ? gK : gV;
            float* dst = basep + ((size_t)(bb * Hh + h) * Nn) * HD + d;
            #pragma unroll
            for (int i = 0; i < 4; i++) {
                const int nr = m_in + i * 16 + g;
                *(float2*)(dst + (size_t)nr * HD) =
                    make_float2(c[i][j][0], c[i][j][1]);
                *(float2*)(dst + (size_t)(nr + 8) * HD) =
                    make_float2(c[i][j][2], c[i][j][3]);
            }
        }
    }
}

// ---------------------------------------------------------------------------
// Fast exp for x <= 0 (post max-subtraction): pure-FFMA 2^f
// ---------------------------------------------------------------------------
__device__ __forceinline__ float exp_nm(float x) {
    x = fmaxf(x, -80.0f);
    const float L2E = 1.4426950408889634f;
    float y = x * L2E;
    float r = rintf(y);
    float f = fmaf(x, L2E, -r);
    float p = 1.5403530e-4f;
    p = fmaf(p, f, 1.3333558e-3f);
    p = fmaf(p, f, 9.6181291e-3f);
    p = fmaf(p, f, 5.5504109e-2f);
    p = fmaf(p, f, 2.4022650e-1f);
    p = fmaf(p, f, 6.9314718e-1f);
    p = fmaf(p, f, 1.0f);
    int e = (int)r;
    float sc = __int_as_float((e + 127) << 23);
    return p * sc;
}

// ---------------------------------------------------------------------------
// Tensor-core fused attention. One block = (b,h, 64-row slab), 256 threads.
// Computes S^T = K Q^T (tf32 mma) into padded fp32 SMEM (stride 516 makes
// B-fragment LDS conflict-free), fp32 softmax in place, O^T = V^T P^T (tf32
// mma, P^T fragments read directly from the padded score array).
// ---------------------------------------------------------------------------
#define SSTR   516             // padded words per score row (4 mod 32)
#define SQSTR  68              // padded words per Q row
#define KF_S   1028            // K-frag k8 stride (8 m16 * 128 + 4)
#define VF_S   516             // V-frag k8 stride (4 m16 * 128 + 4)
#define KVF_WORDS 8256         // max(8*KF_S=8224, 16*VF_S=8256)
#define ATTN_SMEM_BYTES ((64*SSTR + KVF_WORDS + 64*SQSTR + 576) * 4)

__global__ void __launch_bounds__(256) attn_tc_kernel(const float* __restrict__ bias_table)
{
    const int rb = blockIdx.x;       // 0..7 row slab
    const int bh = blockIdx.y;       // 0..767
    const int h  = bh % Hh;
    const int b  = bh / Hh;

    extern __shared__ float sm[];
    float*    sS  = sm;                                  // [64][516] scores/P
    uint32_t* sKV = (uint32_t*)(sm + 64 * SSTR);          // fragment buffer
    uint32_t* sQf = (uint32_t*)(sm + 64 * SSTR + KVF_WORDS); // [64][68] tf32 Q
    float*    sB  = sm + 64 * SSTR + KVF_WORDS + 64 * SQSTR; // bias LUT

    const int tid  = threadIdx.x;
    const int lane = tid & 31;
    const int w    = tid >> 5;
    const int g    = lane >> 2;
    const int tq   = lane & 3;

    const float* Qg = gQ + ((size_t)bh * Nn + rb * 64) * HD;
    const float* Kg = gK + (size_t)bh * Nn * HD;
    const float* Vg = gV + (size_t)bh * Nn * HD;

    // Q (64x64) -> sQf row-major stride 68, pre-converted tf32
    #pragma unroll
    for (int u = 0; u < 4; u++) {
        int idx = tid + 256 * u;           // 1024 float4
        int row = idx >> 4;
        int d0  = (idx & 15) << 2;
        float4 v = *(const float4*)(Qg + row * HD + d0);
        sQf[row*SQSTR + d0+0] = f2tf32(v.x);
        sQf[row*SQSTR + d0+1] = f2tf32(v.y);
        sQf[row*SQSTR + d0+2] = f2tf32(v.z);
        sQf[row*SQSTR + d0+3] = f2tf32(v.w);
    }
    // bias LUT: o = row - col + 511
    for (int o = tid; o < 575; o += 256)
        sB[o] = bias_table[(o + rb * 64) * Hh + h];

    // ---- S^T = K Q^T, per 128-col chunk; warp grid 4m x 2n, tile m32 x n32
    const int wmq = w & 3, wnq = w >> 2;
    for (int kt = 0; kt < 4; kt++) {
        __syncthreads();
        // stage K chunk (128 x 64) into A-fragment layout, tf32
        #pragma unroll
        for (int u = 0; u < 8; u++) {
            int flat = tid + 256 * u;          // 2048 float4
            int row = flat >> 4, kc = (flat & 15) << 2;
            float4 v = *(const float4*)(Kg + (size_t)(kt*128 + row) * HD + kc);
            int k8 = kc >> 3, half = (kc >> 2) & 1;
            int m16 = row >> 4, r = row & 15;
            int base = k8*KF_S + (m16*32 + 4*(r & 7))*4 + (r >> 3) + 2*half;
            sKV[base + 0]  = f2tf32(v.x);
            sKV[base + 4]  = f2tf32(v.y);
            sKV[base + 8]  = f2tf32(v.z);
            sKV[base + 12] = f2tf32(v.w);
        }
        __syncthreads();

        float c[2][4][4];
        #pragma unroll
        for (int i = 0; i < 2; i++)
            #pragma unroll
            for (int j = 0; j < 4; j++)
                #pragma unroll
                for (int r = 0; r < 4; r++) c[i][j][r] = 0.0f;

        #pragma unroll
        for (int k8 = 0; k8 < 8; k8++) {
            uint32_t a[2][4], bfr[4][2];
            #pragma unroll
            for (int i = 0; i < 2; i++) {
                const uint4 va = *(const uint4*)
                    &sKV[k8*KF_S + ((wmq*2 + i)*32 + lane)*4];
                a[i][0]=va.x; a[i][1]=va.y; a[i][2]=va.z; a[i][3]=va.w;
            }
            #pragma unroll
            for (int j = 0; j < 4; j++) {
                const int nrow = (wnq*4 + j)*8 + g;
                const uint32_t* p = &sQf[nrow*SQSTR + k8*8 + tq];
                bfr[j][0] = p[0]; bfr[j][1] = p[4];
            }
            #pragma unroll
            for (int i = 0; i < 2; i++)
                #pragma unroll
                for (int j = 0; j < 4; j++)
                    mma_tf32(c[i][j], a[i], bfr[j]);
        }
        // write S^T chunk -> sS[row][col], scale + bias
        #pragma unroll
        for (int i = 0; i < 2; i++) {
            #pragma unroll
            for (int j = 0; j < 4; j++) {
                const int m0 = kt*128 + wmq*32 + i*16 + g;   // col
                const int n0 = wnq*32 + j*8 + 2*tq;          // row
                sS[(size_t)n0*SSTR + m0]       = fmaf(c[i][j][0], 0.125f, sB[n0     - m0 + 511]);
                sS[(size_t)(n0+1)*SSTR + m0]   = fmaf(c[i][j][1], 0.125f, sB[n0 + 1 - m0 + 511]);
                sS[(size_t)n0*SSTR + m0+8]     = fmaf(c[i][j][2], 0.125f, sB[n0     - m0 + 503]);
                sS[(size_t)(n0+1)*SSTR + m0+8] = fmaf(c[i][j][3], 0.125f, sB[n0 + 1 - m0 + 503]);
            }
        }
    }
    __syncthreads();

    // ---- softmax (fp32, in place; each warp owns 8 rows) ----
    {
        for (int rr = 0; rr < 8; rr++) {
            const int row = w * 8 + rr;
            float v[16];
            float mx = -1e30f;
            #pragma unroll
            for (int u = 0; u < 16; u++) {
                v[u] = sS[(size_t)row*SSTR + lane + 32*u];
                mx = fmaxf(mx, v[u]);
            }
            #pragma unroll
            for (int o = 16; o >= 1; o >>= 1)
                mx = fmaxf(mx, __shfl_xor_sync(0xffffffffu, mx, o));
            float s = 0.0f;
            #pragma unroll
            for (int u = 0; u < 16; u++) { v[u] = exp_nm(v[u] - mx); s += v[u]; }
            #pragma unroll
            for (int o = 16; o >= 1; o >>= 1)
                s += __shfl_xor_sync(0xffffffffu, s, o);
            float inv = 1.0f / s;
            #pragma unroll
            for (int u = 0; u < 16; u++)
                sS[(size_t)row*SSTR + lane + 32*u] = v[u] * inv;
        }
    }

    // ---- O^T = V^T P^T, per 128-k chunk; warp grid 2m x 4n, tile m32 x n16
    const int wmp = w & 1, wnp = w >> 1;
    float oc[2][2][4];
    #pragma unroll
    for (int i = 0; i < 2; i++)
        #pragma unroll
        for (int j = 0; j < 2; j++)
            #pragma unroll
            for (int r = 0; r < 4; r++) oc[i][j][r] = 0.0f;

    for (int vt = 0; vt < 4; vt++) {
        __syncthreads();   // prev-phase sKV reads + softmax writes complete
        // stage V chunk transposed into A-fragment layout (A = V^T), tf32
        #pragma unroll
        for (int u = 0; u < 8; u++) {
            int flat = tid + 256 * u;          // 2048 float4
            int j = flat >> 4, d0 = (flat & 15) << 2;
            float4 v = *(const float4*)(Vg + (size_t)(vt*128 + j) * HD + d0);
            int k8 = j >> 3, kk = j & 7;
            const float vv[4] = {v.x, v.y, v.z, v.w};
            #pragma unroll
            for (int e = 0; e < 4; e++) {
                int d = d0 + e;
                int m16 = d >> 4, r = d & 15;
                int addr = k8*VF_S + (m16*32 + 4*(r & 7) + (kk & 3))*4
                         + (r >> 3) + 2*(kk >> 2);
                sKV[addr] = f2tf32(vv[e]);
            }
        }
        __syncthreads();

        #pragma unroll
        for (int k8 = 0; k8 < 16; k8++) {
            uint32_t a[2][4], bfr[2][2];
            #pragma unroll
            for (int i = 0; i < 2; i++) {
                const uint4 va = *(const uint4*)
                    &sKV[k8*VF_S + ((wmp*2 + i)*32 + lane)*4];
                a[i][0]=va.x; a[i][1]=va.y; a[i][2]=va.z; a[i][3]=va.w;
            }
            #pragma unroll
            for (int j = 0; j < 2; j++) {
                const int nrow = (wnp*2 + j)*8 + g;
                const float* p = &sS[(size_t)nrow*SSTR + vt*128 + k8*8 + tq];
                bfr[j][0] = f2tf32(p[0]);
                bfr[j][1] = f2tf32(p[4]);
            }
            #pragma unroll
            for (int i = 0; i < 2; i++)
                #pragma unroll
                for (int j = 0; j < 2; j++)
                    mma_tf32(oc[i][j], a[i], bfr[j]);
        }
    }

    // write O (transposed C): C[d][row] -> gAO[b, rb*64+row, h*64+d]
    float* Og = gAO + ((size_t)(b * Nn + rb * 64)) * Cc + h * HD;
    #pragma unroll
    for (int i = 0; i < 2; i++) {
        #pragma unroll
        for (int j = 0; j < 2; j++) {
            const int d0v = wmp*32 + i*16 + g;
            const int r0  = wnp*16 + j*8 + 2*tq;
            Og[(size_t)r0*Cc + d0v]         = oc[i][j][0];
            Og[(size_t)(r0+1)*Cc + d0v]     = oc[i][j][1];
            Og[(size_t)r0*Cc + d0v + 8]     = oc[i][j][2];
            Og[(size_t)(r0+1)*Cc + d0v + 8] = oc[i][j][3];
        }
    }
}

extern "C" void kernel_launch(void* const* d_in, const int* in_sizes, int n_in,
                              void* d_out, int out_size)
{
    (void)in_sizes; (void)n_in; (void)out_size;
    const float* x          = (const float*)d_in[0];
    const float* qkv_w      = (const float*)d_in[1];
    const float* proj_w     = (const float*)d_in[2];
    const float* proj_b     = (const float*)d_in[3];
    const float* bias_table = (const float*)d_in[4];
    float* out = (float*)d_out;

    cudaFuncSetAttribute(attn_tc_kernel,
        cudaFuncAttributeMaxDynamicSharedMemorySize, ATTN_SMEM_BYTES);

    void* gAO_ptr = nullptr;
    cudaGetSymbolAddress(&gAO_ptr, gAO);

    // 1) QKV projection (tf32 tensor cores) with scatter into gQ/gK/gV
    gemm_tf32<1><<<dim3(3*Cc/128, Mrows/128), 256>>>(
        x, qkv_w, nullptr, nullptr, Mrows, 3*Cc, Cc);

    // 2) Fused attention (tf32 tensor cores + fp32 softmax)
    attn_tc_kernel<<<dim3(Nn/64, BH), 256, ATTN_SMEM_BYTES>>>(bias_table);

    // 3) Output projection (tf32 tensor cores)
    gemm_tf32<0><<<dim3(Cc/128, Mrows/128), 256>>>(
        (const float*)gAO_ptr, proj_w, proj_b, out, Mrows, Cc, Cc);
}